// round 3
// baseline (speedup 1.0000x reference)
#include <cuda_runtime.h>
#include <math.h>
#include <stdint.h>

// ---------------- problem constants ----------------
#define BATCH 64
#define Hdim  56
#define Wdim  56
#define Cdim  128
#define HEADS 4
#define WSz   7
#define WS2   49
#define HID   512
#define NWG   9
#define NTOK  (BATCH*Hdim*Wdim)     // 200704
#define NWIN  (BATCH*NWG*NWG)       // 5184

// ---------------- scratch ----------------
__device__ float g_xn[(size_t)NTOK * Cdim];
__device__ float g_x2[(size_t)NTOK * Cdim];
__device__ float g_h [(size_t)NTOK * HID];

// =====================================================================
// Fused: LN1 -> shifted-window token mixing -> +residual -> LN2
// One block per 7x7 window (windows are disjoint and cover all tokens).
// Outputs: x2 (residual stream), xn2 (LN2 output = GEMM input).
// =====================================================================
#define WPAD 52   // padded weight row (49 -> 52 floats, 16B-aligned rows)
#define PRE_SMEM ((2*WS2*Cdim + HEADS*WS2*WPAD) * 4)   // 90944 B

__global__ void __launch_bounds__(256, 2) fused_pre(
    const float* __restrict__ x,
    const float* __restrict__ g1, const float* __restrict__ b1,
    const float* __restrict__ sw, const float* __restrict__ sb,
    const float* __restrict__ g2, const float* __restrict__ b2,
    float* __restrict__ x2, float* __restrict__ xn2)
{
    extern __shared__ float sm[];
    float* s_x = sm;                    // [49][128] raw x (later x2)
    float* s_n = sm + WS2 * Cdim;       // [49][128] LN1 output
    float* s_w = sm + 2 * WS2 * Cdim;   // [4*49][52] weights

    const int tid  = threadIdx.x;
    const int lane = tid & 31;
    const int warp = tid >> 5;

    const int win = blockIdx.x;
    const int b   = win / 81;
    const int wi  = win % 81;
    const int wh  = wi / 9, ww = wi % 9;

    const int c0 = lane * 4;             // channel group per lane
    const int headL = lane >> 3;         // head for this lane's channels

    const float4 g1v = *(const float4*)(g1 + c0);
    const float4 b1v = *(const float4*)(b1 + c0);
    const float4 g2v = *(const float4*)(g2 + c0);
    const float4 b2v = *(const float4*)(b2 + c0);

    // ---- load x tile (zero outside image: pad-after-LN semantics) ----
    for (int idx = tid; idx < WS2 * Cdim; idx += 256) {
        int j = idx >> 7, c = idx & 127;
        int hs = wh * 7 + j / 7 - 4;
        int ws = ww * 7 + j % 7 - 4;
        float v = 0.0f;
        if ((unsigned)hs < 56u && (unsigned)ws < 56u)
            v = x[((size_t)b * 3136 + hs * 56 + ws) * 128 + c];
        s_x[idx] = v;
    }
    // ---- load weights into padded rows ----
    for (int idx = tid; idx < HEADS * WS2 * WS2; idx += 256) {
        int row = idx / 49, j = idx % 49;
        s_w[row * WPAD + j] = sw[idx];
    }
    __syncthreads();

    // ---- LN1 per token (warp handles i = warp, warp+8, ...) ----
    #pragma unroll
    for (int ii = 0; ii < 7; ii++) {
        int i = warp + 8 * ii;
        if (i >= 49) continue;                      // warp-uniform
        int hs = wh * 7 + i / 7 - 4;
        int ws = ww * 7 + i % 7 - 4;
        bool valid = ((unsigned)hs < 56u) && ((unsigned)ws < 56u);  // warp-uniform
        float4 o4 = make_float4(0.f, 0.f, 0.f, 0.f);
        if (valid) {
            float4 v = *(float4*)(s_x + i * 128 + c0);
            float s  = v.x + v.y + v.z + v.w;
            float s2 = v.x*v.x + v.y*v.y + v.z*v.z + v.w*v.w;
            #pragma unroll
            for (int o = 16; o; o >>= 1) {
                s  += __shfl_xor_sync(0xffffffffu, s,  o);
                s2 += __shfl_xor_sync(0xffffffffu, s2, o);
            }
            float mu  = s * (1.0f / 128.0f);
            float inv = rsqrtf(s2 * (1.0f / 128.0f) - mu * mu + 1e-5f);
            o4.x = (v.x - mu) * inv * g1v.x + b1v.x;
            o4.y = (v.y - mu) * inv * g1v.y + b1v.y;
            o4.z = (v.z - mu) * inv * g1v.z + b1v.z;
            o4.w = (v.w - mu) * inv * g1v.w + b1v.w;
        }
        *(float4*)(s_n + i * 128 + c0) = o4;
    }
    __syncthreads();

    // ---- token mixing: y[i][c] = sum_j w[h,i,j]*xn[j][c] + sb[h,i] ----
    float4 acc[7];
    #pragma unroll
    for (int ii = 0; ii < 7; ii++) {
        int i = warp + 8 * ii;
        float bv = (i < 49) ? sb[headL * 49 + i] : 0.0f;
        acc[ii] = make_float4(bv, bv, bv, bv);
    }
    for (int j0 = 0; j0 < 48; j0 += 4) {
        float4 xv0 = *(float4*)(s_n + (j0 + 0) * 128 + c0);
        float4 xv1 = *(float4*)(s_n + (j0 + 1) * 128 + c0);
        float4 xv2 = *(float4*)(s_n + (j0 + 2) * 128 + c0);
        float4 xv3 = *(float4*)(s_n + (j0 + 3) * 128 + c0);
        #pragma unroll
        for (int ii = 0; ii < 7; ii++) {
            int i = warp + 8 * ii;
            if (i >= 49) continue;
            float4 wv = *(float4*)(s_w + (headL * 49 + i) * WPAD + j0);
            acc[ii].x += wv.x*xv0.x + wv.y*xv1.x + wv.z*xv2.x + wv.w*xv3.x;
            acc[ii].y += wv.x*xv0.y + wv.y*xv1.y + wv.z*xv2.y + wv.w*xv3.y;
            acc[ii].z += wv.x*xv0.z + wv.y*xv1.z + wv.z*xv2.z + wv.w*xv3.z;
            acc[ii].w += wv.x*xv0.w + wv.y*xv1.w + wv.z*xv2.w + wv.w*xv3.w;
        }
    }
    {   // remainder j = 48
        float4 xv = *(float4*)(s_n + 48 * 128 + c0);
        #pragma unroll
        for (int ii = 0; ii < 7; ii++) {
            int i = warp + 8 * ii;
            if (i >= 49) continue;
            float wv = s_w[(headL * 49 + i) * WPAD + 48];
            acc[ii].x += wv * xv.x; acc[ii].y += wv * xv.y;
            acc[ii].z += wv * xv.z; acc[ii].w += wv * xv.w;
        }
    }
    // residual: x2 = x + y (into s_x; each element touched only by its owner)
    #pragma unroll
    for (int ii = 0; ii < 7; ii++) {
        int i = warp + 8 * ii;
        if (i >= 49) continue;
        float4 xr = *(float4*)(s_x + i * 128 + c0);
        xr.x += acc[ii].x; xr.y += acc[ii].y;
        xr.z += acc[ii].z; xr.w += acc[ii].w;
        *(float4*)(s_x + i * 128 + c0) = xr;
    }
    __syncthreads();

    // ---- LN2 + global writes (valid tokens only) ----
    #pragma unroll
    for (int ii = 0; ii < 7; ii++) {
        int i = warp + 8 * ii;
        if (i >= 49) continue;
        int hs = wh * 7 + i / 7 - 4;
        int ws = ww * 7 + i % 7 - 4;
        if ((unsigned)hs >= 56u || (unsigned)ws >= 56u) continue;  // warp-uniform
        float4 v = *(float4*)(s_x + i * 128 + c0);
        float s  = v.x + v.y + v.z + v.w;
        float s2 = v.x*v.x + v.y*v.y + v.z*v.z + v.w*v.w;
        #pragma unroll
        for (int o = 16; o; o >>= 1) {
            s  += __shfl_xor_sync(0xffffffffu, s,  o);
            s2 += __shfl_xor_sync(0xffffffffu, s2, o);
        }
        float mu  = s * (1.0f / 128.0f);
        float inv = rsqrtf(s2 * (1.0f / 128.0f) - mu * mu + 1e-5f);
        size_t o = ((size_t)b * 3136 + hs * 56 + ws) * 128 + c0;
        *(float4*)(x2 + o) = v;
        float4 n4;
        n4.x = (v.x - mu) * inv * g2v.x + b2v.x;
        n4.y = (v.y - mu) * inv * g2v.y + b2v.y;
        n4.z = (v.z - mu) * inv * g2v.z + b2v.z;
        n4.w = (v.w - mu) * inv * g2v.w + b2v.w;
        *(float4*)(xn2 + o) = n4;
    }
}

// =====================================================================
// tf32 tensor-core GEMM: BM=128 BN=64 BK=32, 8 warps (4x2), warp=32x32.
// cp.async double-buffered. MODE 0: gelu(A@B+bias). MODE 1: res+(A@B+bias).
// =====================================================================
__device__ __forceinline__ uint32_t f2tf(float f) {
    uint32_t u;
    asm("cvt.rna.tf32.f32 %0, %1;" : "=r"(u) : "f"(f));
    return u;
}
__device__ __forceinline__ void cpasync16(uint32_t s, const void* g) {
    asm volatile("cp.async.cg.shared.global [%0], [%1], 16;\n" :: "r"(s), "l"(g));
}
__device__ __forceinline__ float gelu_exact(float v) {
    return 0.5f * v * (1.0f + erff(v * 0.70710678118654752f));
}

#define AST 36
#define BST 68
#define GEMM_SMEM ((2*128*AST + 2*32*BST) * 4)   // 54272 B

template<int Kd, int Nd, int MODE>
__global__ void __launch_bounds__(256)
gemm_tc(const float* __restrict__ A, const float* __restrict__ Bw,
        const float* __restrict__ bias, const float* __restrict__ res,
        float* __restrict__ out)
{
    constexpr int BM = 128, BN = 64, BK = 32;
    extern __shared__ float smem[];
    float* s_a = smem;                  // [2][128][AST]
    float* s_b = smem + 2 * BM * AST;   // [2][32][BST]

    const int tid  = threadIdx.x;
    const int lane = tid & 31;
    const int warp = tid >> 5;
    const int wm = warp >> 1, wn = warp & 1;
    const int bm = blockIdx.y * BM, bn = blockIdx.x * BN;
    const int t4 = lane >> 2, q = lane & 3;

    const uint32_t sa_s = (uint32_t)__cvta_generic_to_shared(s_a);
    const uint32_t sb_s = (uint32_t)__cvta_generic_to_shared(s_b);

    float acc[2][4][4];
    #pragma unroll
    for (int mi = 0; mi < 2; mi++)
        #pragma unroll
        for (int ni = 0; ni < 4; ni++)
            #pragma unroll
            for (int r = 0; r < 4; r++) acc[mi][ni][r] = 0.0f;

    auto loadAB = [&](int buf, int k0) {
        #pragma unroll
        for (int i = 0; i < 4; i++) {         // A: 1024 16B lines
            int l = tid + 256 * i;
            int r = l >> 3, cq = (l & 7) * 4;
            cpasync16(sa_s + (uint32_t)(((buf * BM + r) * AST + cq) * 4),
                      A + (size_t)(bm + r) * Kd + k0 + cq);
        }
        #pragma unroll
        for (int i = 0; i < 2; i++) {         // B: 512 16B lines
            int l = tid + 256 * i;
            int r = l >> 4, cq = (l & 15) * 4;
            cpasync16(sb_s + (uint32_t)(((buf * BK + r) * BST + cq) * 4),
                      Bw + (size_t)(k0 + r) * Nd + bn + cq);
        }
        asm volatile("cp.async.commit_group;\n");
    };

    constexpr int KT = Kd / BK;
    loadAB(0, 0);
    asm volatile("cp.async.wait_group 0;\n");
    __syncthreads();

    int buf = 0;
    for (int kt = 0; kt < KT; kt++) {
        if (kt + 1 < KT) loadAB(buf ^ 1, (kt + 1) * BK);

        const float* sa = s_a + buf * BM * AST;
        const float* sb = s_b + buf * BK * BST;
        #pragma unroll
        for (int ks = 0; ks < 4; ks++) {
            const int k = ks * 8;
            uint32_t a[2][4], bf[4][2];
            #pragma unroll
            for (int mi = 0; mi < 2; mi++) {
                int r = wm * 32 + mi * 16 + t4;
                a[mi][0] = f2tf(sa[(r    ) * AST + k + q    ]);
                a[mi][1] = f2tf(sa[(r + 8) * AST + k + q    ]);
                a[mi][2] = f2tf(sa[(r    ) * AST + k + q + 4]);
                a[mi][3] = f2tf(sa[(r + 8) * AST + k + q + 4]);
            }
            #pragma unroll
            for (int ni = 0; ni < 4; ni++) {
                int cc = wn * 32 + ni * 8 + t4;
                bf[ni][0] = f2tf(sb[(k + q    ) * BST + cc]);
                bf[ni][1] = f2tf(sb[(k + q + 4) * BST + cc]);
            }
            #pragma unroll
            for (int mi = 0; mi < 2; mi++)
                #pragma unroll
                for (int ni = 0; ni < 4; ni++)
                    asm volatile(
                        "mma.sync.aligned.m16n8k8.row.col.f32.tf32.tf32.f32 "
                        "{%0,%1,%2,%3},{%4,%5,%6,%7},{%8,%9},{%0,%1,%2,%3};\n"
                        : "+f"(acc[mi][ni][0]), "+f"(acc[mi][ni][1]),
                          "+f"(acc[mi][ni][2]), "+f"(acc[mi][ni][3])
                        : "r"(a[mi][0]), "r"(a[mi][1]), "r"(a[mi][2]), "r"(a[mi][3]),
                          "r"(bf[ni][0]), "r"(bf[ni][1]));
        }
        if (kt + 1 < KT) asm volatile("cp.async.wait_group 0;\n");
        __syncthreads();
        buf ^= 1;
    }

    // ---- epilogue ----
    #pragma unroll
    for (int mi = 0; mi < 2; mi++) {
        #pragma unroll
        for (int ni = 0; ni < 4; ni++) {
            int cc = bn + wn * 32 + ni * 8 + q * 2;
            int r0 = bm + wm * 32 + mi * 16 + t4;
            int r1 = r0 + 8;
            float bs0 = bias[cc], bs1 = bias[cc + 1];
            float2 v0 = make_float2(acc[mi][ni][0] + bs0, acc[mi][ni][1] + bs1);
            float2 v1 = make_float2(acc[mi][ni][2] + bs0, acc[mi][ni][3] + bs1);
            if (MODE == 0) {
                v0.x = gelu_exact(v0.x); v0.y = gelu_exact(v0.y);
                v1.x = gelu_exact(v1.x); v1.y = gelu_exact(v1.y);
            } else {
                float2 r0v = *(const float2*)(res + (size_t)r0 * Nd + cc);
                float2 r1v = *(const float2*)(res + (size_t)r1 * Nd + cc);
                v0.x += r0v.x; v0.y += r0v.y;
                v1.x += r1v.x; v1.y += r1v.y;
            }
            *(float2*)(out + (size_t)r0 * Nd + cc) = v0;
            *(float2*)(out + (size_t)r1 * Nd + cc) = v1;
        }
    }
}

// ---------------- launch ----------------
extern "C" void kernel_launch(void* const* d_in, const int* in_sizes, int n_in,
                              void* d_out, int out_size)
{
    const float* x   = (const float*)d_in[0];
    const float* g1  = (const float*)d_in[1];
    const float* b1  = (const float*)d_in[2];
    const float* sw  = (const float*)d_in[3];
    const float* sb  = (const float*)d_in[4];
    const float* g2  = (const float*)d_in[5];
    const float* b2  = (const float*)d_in[6];
    const float* w1  = (const float*)d_in[7];
    const float* bb1 = (const float*)d_in[8];
    const float* w2  = (const float*)d_in[9];
    const float* bb2 = (const float*)d_in[10];
    float* out = (float*)d_out;

    float *xn, *x2, *hbuf;
    cudaGetSymbolAddress((void**)&xn,   g_xn);
    cudaGetSymbolAddress((void**)&x2,   g_x2);
    cudaGetSymbolAddress((void**)&hbuf, g_h);

    cudaFuncSetAttribute(fused_pre,
                         cudaFuncAttributeMaxDynamicSharedMemorySize, PRE_SMEM);
    cudaFuncSetAttribute(gemm_tc<Cdim, HID, 0>,
                         cudaFuncAttributeMaxDynamicSharedMemorySize, GEMM_SMEM);
    cudaFuncSetAttribute(gemm_tc<HID, Cdim, 1>,
                         cudaFuncAttributeMaxDynamicSharedMemorySize, GEMM_SMEM);

    // 1) fused LN1 + window mixing + residual + LN2
    fused_pre<<<NWIN, 256, PRE_SMEM>>>(x, g1, b1, sw, sb, g2, b2, x2, xn);
    // 2) fc1 + GELU : (200704x128) @ (128x512)
    gemm_tc<Cdim, HID, 0><<<dim3(HID / 64, NTOK / 128), 256, GEMM_SMEM>>>(xn, w1, bb1, nullptr, hbuf);
    // 3) fc2 + residual : (200704x512) @ (512x128) + x2
    gemm_tc<HID, Cdim, 1><<<dim3(Cdim / 64, NTOK / 128), 256, GEMM_SMEM>>>(hbuf, w2, bb2, x2, out);
}

// round 5
// speedup vs baseline: 1.4362x; 1.4362x over previous
#include <cuda_runtime.h>
#include <cuda_bf16.h>
#include <math.h>
#include <stdint.h>

#define NTOK 200704
#define NWIN 5184
#define WS2  49
#define WPAD 52

__device__ __nv_bfloat16 g_xn [(size_t)NTOK * 128];
__device__ float         g_x2 [(size_t)NTOK * 128];
__device__ __nv_bfloat16 g_h  [(size_t)NTOK * 512];
__device__ __nv_bfloat16 g_w1t[512 * 128];   // [n][k]
__device__ __nv_bfloat16 g_w2t[128 * 512];   // [n][k]

__device__ __forceinline__ void cpasync16(uint32_t s, const void* g) {
    asm volatile("cp.async.cg.shared.global [%0], [%1], 16;\n" :: "r"(s), "l"(g));
}
__device__ __forceinline__ void cp_commit() { asm volatile("cp.async.commit_group;"); }
template<int N> __device__ __forceinline__ void cp_wait() {
    asm volatile("cp.async.wait_group %0;" :: "n"(N));
}
__device__ __forceinline__ uint32_t pack_bf16(float lo, float hi) {
    uint32_t r; asm("cvt.rn.bf16x2.f32 %0, %1, %2;" : "=r"(r) : "f"(hi), "f"(lo)); return r;
}
__device__ __forceinline__ float gelu_exact(float v) {
    return 0.5f * v * (1.0f + erff(v * 0.70710678118654752f));
}

// ---------- weight prep: transpose + bf16 ----------
__global__ void prep_weights(const float* __restrict__ w1, const float* __restrict__ w2)
{
    int t = blockIdx.x * 256 + threadIdx.x;
    if (t < 512 * 128) {
        int n = t >> 7, k = t & 127;
        g_w1t[t] = __float2bfloat16(w1[k * 512 + n]);
        int n2 = t >> 9, k2 = t & 511;
        g_w2t[t] = __float2bfloat16(w2[k2 * 128 + n2]);
    }
}

// ---------- fused LN1 + window mix + residual + LN2 ----------
#define PRE_SMEM ((WS2*128 + 4*WS2*WPAD) * 4)   // 65856 B -> 3 CTA/SM

__global__ void __launch_bounds__(256, 3) fused_pre(
    const float* __restrict__ x,
    const float* __restrict__ g1, const float* __restrict__ b1,
    const float* __restrict__ sw, const float* __restrict__ sb,
    const float* __restrict__ g2, const float* __restrict__ b2)
{
    extern __shared__ float sm[];
    float* s_n = sm;               // [49][128]
    float* s_w = sm + WS2 * 128;   // [196][52]

    const int tid = threadIdx.x, lane = tid & 31, warp = tid >> 5;
    const int win = blockIdx.x;
    const int b = win / 81, wi = win % 81;
    const int wh = wi / 9, ww = wi % 9;
    const int c0 = lane * 4, headL = lane >> 3;

    for (int idx = tid; idx < WS2 * 128; idx += 256) {
        int j = idx >> 7, c = idx & 127;
        int hs = wh * 7 + j / 7 - 4, ws = ww * 7 + j % 7 - 4;
        float v = 0.0f;
        if ((unsigned)hs < 56u && (unsigned)ws < 56u)
            v = x[((size_t)b * 3136 + hs * 56 + ws) * 128 + c];
        s_n[idx] = v;
    }
    for (int idx = tid; idx < 4 * WS2 * WS2; idx += 256)
        s_w[(idx / 49) * WPAD + idx % 49] = sw[idx];
    __syncthreads();

    {   // LN1 in place (pad rows stay zero)
        const float4 g1v = *(const float4*)(g1 + c0);
        const float4 b1v = *(const float4*)(b1 + c0);
        #pragma unroll
        for (int ii = 0; ii < 7; ii++) {
            int i = warp + 8 * ii;
            if (i >= 49) continue;
            int hs = wh * 7 + i / 7 - 4, ws = ww * 7 + i % 7 - 4;
            if ((unsigned)hs >= 56u || (unsigned)ws >= 56u) continue;
            float4 v = *(float4*)(s_n + i * 128 + c0);
            float s = v.x + v.y + v.z + v.w;
            float s2 = v.x*v.x + v.y*v.y + v.z*v.z + v.w*v.w;
            #pragma unroll
            for (int o = 16; o; o >>= 1) {
                s  += __shfl_xor_sync(0xffffffffu, s,  o);
                s2 += __shfl_xor_sync(0xffffffffu, s2, o);
            }
            float mu = s * 0.0078125f;
            float inv = rsqrtf(s2 * 0.0078125f - mu * mu + 1e-5f);
            v.x = (v.x - mu) * inv * g1v.x + b1v.x;
            v.y = (v.y - mu) * inv * g1v.y + b1v.y;
            v.z = (v.z - mu) * inv * g1v.z + b1v.z;
            v.w = (v.w - mu) * inv * g1v.w + b1v.w;
            *(float4*)(s_n + i * 128 + c0) = v;
        }
    }
    __syncthreads();

    float4 acc[7];
    #pragma unroll
    for (int ii = 0; ii < 7; ii++) {
        int i = warp + 8 * ii;
        float bv = (i < 49) ? sb[headL * 49 + i] : 0.0f;
        acc[ii] = make_float4(bv, bv, bv, bv);
    }
    for (int j0 = 0; j0 < 48; j0 += 4) {
        float4 x0 = *(float4*)(s_n + (j0+0)*128 + c0);
        float4 x1 = *(float4*)(s_n + (j0+1)*128 + c0);
        float4 x2v = *(float4*)(s_n + (j0+2)*128 + c0);
        float4 x3 = *(float4*)(s_n + (j0+3)*128 + c0);
        #pragma unroll
        for (int ii = 0; ii < 7; ii++) {
            int i = warp + 8 * ii;
            if (i >= 49) continue;
            float4 wv = *(float4*)(s_w + (headL*49 + i)*WPAD + j0);
            acc[ii].x += wv.x*x0.x + wv.y*x1.x + wv.z*x2v.x + wv.w*x3.x;
            acc[ii].y += wv.x*x0.y + wv.y*x1.y + wv.z*x2v.y + wv.w*x3.y;
            acc[ii].z += wv.x*x0.z + wv.y*x1.z + wv.z*x2v.z + wv.w*x3.z;
            acc[ii].w += wv.x*x0.w + wv.y*x1.w + wv.z*x2v.w + wv.w*x3.w;
        }
    }
    {
        float4 xv = *(float4*)(s_n + 48*128 + c0);
        #pragma unroll
        for (int ii = 0; ii < 7; ii++) {
            int i = warp + 8 * ii;
            if (i >= 49) continue;
            float wv = s_w[(headL*49 + i)*WPAD + 48];
            acc[ii].x += wv*xv.x; acc[ii].y += wv*xv.y;
            acc[ii].z += wv*xv.z; acc[ii].w += wv*xv.w;
        }
    }
    {   // residual (re-read x from L2) + LN2 -> g_x2 fp32, g_xn bf16
        const float4 g2v = *(const float4*)(g2 + c0);
        const float4 b2v = *(const float4*)(b2 + c0);
        #pragma unroll
        for (int ii = 0; ii < 7; ii++) {
            int i = warp + 8 * ii;
            if (i >= 49) continue;
            int hs = wh * 7 + i / 7 - 4, ws = ww * 7 + i % 7 - 4;
            if ((unsigned)hs >= 56u || (unsigned)ws >= 56u) continue;
            size_t o = ((size_t)b * 3136 + hs * 56 + ws) * 128 + c0;
            float4 v = *(const float4*)(x + o);
            v.x += acc[ii].x; v.y += acc[ii].y; v.z += acc[ii].z; v.w += acc[ii].w;
            *(float4*)(g_x2 + o) = v;
            float s = v.x + v.y + v.z + v.w;
            float s2 = v.x*v.x + v.y*v.y + v.z*v.z + v.w*v.w;
            #pragma unroll
            for (int os = 16; os; os >>= 1) {
                s  += __shfl_xor_sync(0xffffffffu, s,  os);
                s2 += __shfl_xor_sync(0xffffffffu, s2, os);
            }
            float mu = s * 0.0078125f;
            float inv = rsqrtf(s2 * 0.0078125f - mu * mu + 1e-5f);
            float n0 = (v.x - mu) * inv * g2v.x + b2v.x;
            float n1 = (v.y - mu) * inv * g2v.y + b2v.y;
            float n2 = (v.z - mu) * inv * g2v.z + b2v.z;
            float n3 = (v.w - mu) * inv * g2v.w + b2v.w;
            *(uint2*)(g_xn + o) = make_uint2(pack_bf16(n0, n1), pack_bf16(n2, n3));
        }
    }
}

// =====================================================================
// bf16 mma.sync GEMM: BM=128 BN=128 BK=32, 8 warps (2m x 4n), warp 64x32.
// A [M][K] bf16 row-major, Bt [N][K] bf16 row-major -> mma row.col.
// MODE 0: g_h = gelu(A@B + bias) bf16.  MODE 1: out = res + A@B + bias fp32.
// =====================================================================
#define SSTR 40   // smem row stride in bf16 elems (80B, conflict-free)

template<int Kd, int MODE>
__global__ void __launch_bounds__(256)
gemm_bf16(const __nv_bfloat16* __restrict__ A, const __nv_bfloat16* __restrict__ Bt,
          const float* __restrict__ bias, const float* __restrict__ res,
          float* __restrict__ outf, __nv_bfloat16* __restrict__ outh)
{
    __shared__ __align__(16) __nv_bfloat16 s_a[2][128][SSTR];
    __shared__ __align__(16) __nv_bfloat16 s_b[2][128][SSTR];

    const int tid = threadIdx.x, lane = tid & 31, warp = tid >> 5;
    const int wm = warp >> 2, wn = warp & 3;     // 2 x 4
    const int bm = blockIdx.y * 128, bn = blockIdx.x * 128;
    const int t4 = lane >> 2, q = lane & 3;

    const uint32_t sa_s = (uint32_t)__cvta_generic_to_shared(&s_a[0][0][0]);
    const uint32_t sb_s = (uint32_t)__cvta_generic_to_shared(&s_b[0][0][0]);

    float acc[4][4][4];
    #pragma unroll
    for (int mi = 0; mi < 4; mi++)
        #pragma unroll
        for (int ni = 0; ni < 4; ni++)
            #pragma unroll
            for (int r = 0; r < 4; r++) acc[mi][ni][r] = 0.0f;

    auto loadAB = [&](int buf, int k0) {
        #pragma unroll
        for (int i = 0; i < 2; i++) {
            int l = tid + 256 * i;            // 0..511
            int r = l >> 2, ch = (l & 3) * 8; // 16B chunks
            cpasync16(sa_s + (uint32_t)(((buf * 128 + r) * SSTR + ch) * 2),
                      A + (size_t)(bm + r) * Kd + k0 + ch);
        }
        #pragma unroll
        for (int i = 0; i < 2; i++) {
            int l = tid + 256 * i;
            int r = l >> 2, ch = (l & 3) * 8;
            cpasync16(sb_s + (uint32_t)(((buf * 128 + r) * SSTR + ch) * 2),
                      Bt + (size_t)(bn + r) * Kd + k0 + ch);
        }
        cp_commit();
    };

    constexpr int KT = Kd / 32;
    loadAB(0, 0);
    cp_wait<0>();
    __syncthreads();

    int buf = 0;
    for (int kt = 0; kt < KT; kt++) {
        if (kt + 1 < KT) loadAB(buf ^ 1, (kt + 1) * 32);

        #pragma unroll
        for (int ks = 0; ks < 2; ks++) {
            const int k = ks * 16;
            uint32_t a[4][4], bfr[4][2];
            #pragma unroll
            for (int mi = 0; mi < 4; mi++) {
                int r = wm * 64 + mi * 16 + t4;
                a[mi][0] = *(const uint32_t*)&s_a[buf][r    ][k + 2*q    ];
                a[mi][1] = *(const uint32_t*)&s_a[buf][r + 8][k + 2*q    ];
                a[mi][2] = *(const uint32_t*)&s_a[buf][r    ][k + 2*q + 8];
                a[mi][3] = *(const uint32_t*)&s_a[buf][r + 8][k + 2*q + 8];
            }
            #pragma unroll
            for (int ni = 0; ni < 4; ni++) {
                int n = wn * 32 + ni * 8 + t4;
                bfr[ni][0] = *(const uint32_t*)&s_b[buf][n][k + 2*q    ];
                bfr[ni][1] = *(const uint32_t*)&s_b[buf][n][k + 2*q + 8];
            }
            #pragma unroll
            for (int mi = 0; mi < 4; mi++)
                #pragma unroll
                for (int ni = 0; ni < 4; ni++)
                    asm volatile(
                        "mma.sync.aligned.m16n8k16.row.col.f32.bf16.bf16.f32 "
                        "{%0,%1,%2,%3},{%4,%5,%6,%7},{%8,%9},{%0,%1,%2,%3};\n"
                        : "+f"(acc[mi][ni][0]), "+f"(acc[mi][ni][1]),
                          "+f"(acc[mi][ni][2]), "+f"(acc[mi][ni][3])
                        : "r"(a[mi][0]), "r"(a[mi][1]), "r"(a[mi][2]), "r"(a[mi][3]),
                          "r"(bfr[ni][0]), "r"(bfr[ni][1]));
        }
        if (kt + 1 < KT) cp_wait<0>();
        __syncthreads();
        buf ^= 1;
    }

    // ---- epilogue ----
    #pragma unroll
    for (int mi = 0; mi < 4; mi++) {
        #pragma unroll
        for (int ni = 0; ni < 4; ni++) {
            int col = bn + wn * 32 + ni * 8 + 2 * q;
            int r0 = bm + wm * 64 + mi * 16 + t4;
            int r1 = r0 + 8;
            float bs0 = bias[col], bs1 = bias[col + 1];
            float v0 = acc[mi][ni][0] + bs0, v1 = acc[mi][ni][1] + bs1;
            float v2 = acc[mi][ni][2] + bs0, v3 = acc[mi][ni][3] + bs1;
            if (MODE == 0) {
                *(uint32_t*)&outh[(size_t)r0 * 512 + col] =
                    pack_bf16(gelu_exact(v0), gelu_exact(v1));
                *(uint32_t*)&outh[(size_t)r1 * 512 + col] =
                    pack_bf16(gelu_exact(v2), gelu_exact(v3));
            } else {
                float2 ra = *(const float2*)(res + (size_t)r0 * 128 + col);
                float2 rb = *(const float2*)(res + (size_t)r1 * 128 + col);
                *(float2*)(outf + (size_t)r0 * 128 + col) = make_float2(v0 + ra.x, v1 + ra.y);
                *(float2*)(outf + (size_t)r1 * 128 + col) = make_float2(v2 + rb.x, v3 + rb.y);
            }
        }
    }
}

// ---------- launch ----------
extern "C" void kernel_launch(void* const* d_in, const int* in_sizes, int n_in,
                              void* d_out, int out_size)
{
    const float* x   = (const float*)d_in[0];
    const float* g1  = (const float*)d_in[1];
    const float* b1  = (const float*)d_in[2];
    const float* sw  = (const float*)d_in[3];
    const float* sb  = (const float*)d_in[4];
    const float* g2  = (const float*)d_in[5];
    const float* b2  = (const float*)d_in[6];
    const float* w1  = (const float*)d_in[7];
    const float* bb1 = (const float*)d_in[8];
    const float* w2  = (const float*)d_in[9];
    const float* bb2 = (const float*)d_in[10];
    float* out = (float*)d_out;

    __nv_bfloat16 *xn, *hbuf, *w1t, *w2t;
    float *x2;
    cudaGetSymbolAddress((void**)&xn,   g_xn);
    cudaGetSymbolAddress((void**)&x2,   g_x2);
    cudaGetSymbolAddress((void**)&hbuf, g_h);
    cudaGetSymbolAddress((void**)&w1t,  g_w1t);
    cudaGetSymbolAddress((void**)&w2t,  g_w2t);

    cudaFuncSetAttribute(fused_pre, cudaFuncAttributeMaxDynamicSharedMemorySize, PRE_SMEM);

    prep_weights<<<256, 256>>>(w1, w2);
    fused_pre<<<NWIN, 256, PRE_SMEM>>>(x, g1, b1, sw, sb, g2, b2);
    // fc1: (200704x128)@(128x512) + gelu -> g_h (bf16)
    gemm_bf16<128, 0><<<dim3(4, NTOK / 128), 256>>>(xn, w1t, bb1, nullptr, nullptr, hbuf);
    // fc2: (200704x512)@(512x128) + bias + residual -> out (fp32)
    gemm_bf16<512, 1><<<dim3(1, NTOK / 128), 256>>>(hbuf, w2t, bb2, x2, out, nullptr);
}

// round 7
// speedup vs baseline: 1.7573x; 1.2236x over previous
#include <cuda_runtime.h>
#include <cuda_bf16.h>
#include <math.h>
#include <stdint.h>

#define NTOK 200704
#define NWIN 5184
#define WS2  49
#define WPAD 52

__device__ __nv_bfloat16 g_xn [(size_t)NTOK * 128];
__device__ float         g_x2 [(size_t)NTOK * 128];
__device__ __nv_bfloat16 g_w1t[512 * 128];   // [n][k]
__device__ __nv_bfloat16 g_w2t[128 * 512];   // [n][k]

__device__ __forceinline__ void cpasync16(uint32_t s, const void* g) {
    asm volatile("cp.async.cg.shared.global [%0], [%1], 16;\n" :: "r"(s), "l"(g));
}
__device__ __forceinline__ void cp_commit() { asm volatile("cp.async.commit_group;"); }
template<int N> __device__ __forceinline__ void cp_wait() {
    asm volatile("cp.async.wait_group %0;" :: "n"(N));
}
__device__ __forceinline__ uint32_t pack_bf16(float lo, float hi) {
    uint32_t r; asm("cvt.rn.bf16x2.f32 %0, %1, %2;" : "=r"(r) : "f"(hi), "f"(lo)); return r;
}
__device__ __forceinline__ float gelu_exact(float v) {
    return 0.5f * v * (1.0f + erff(v * 0.70710678118654752f));
}
#define MMA16816(d, a, b0, b1) \
    asm volatile("mma.sync.aligned.m16n8k16.row.col.f32.bf16.bf16.f32 " \
        "{%0,%1,%2,%3},{%4,%5,%6,%7},{%8,%9},{%0,%1,%2,%3};\n" \
        : "+f"((d)[0]), "+f"((d)[1]), "+f"((d)[2]), "+f"((d)[3]) \
        : "r"((a)[0]), "r"((a)[1]), "r"((a)[2]), "r"((a)[3]), "r"(b0), "r"(b1))

// ---------- weight prep ----------
__global__ void prep_weights(const float* __restrict__ w1, const float* __restrict__ w2)
{
    int t = blockIdx.x * 256 + threadIdx.x;
    if (t < 512 * 128) {
        int n = t >> 7, k = t & 127;
        g_w1t[t] = __float2bfloat16(w1[k * 512 + n]);
        int n2 = t >> 9, k2 = t & 511;
        g_w2t[t] = __float2bfloat16(w2[k2 * 128 + n2]);
    }
}

// ---------- fused LN1 + window mix + residual + LN2 ----------
#define PRE_SMEM ((WS2*128 + 4*WS2*WPAD) * 4)   // 65856 B

__global__ void __launch_bounds__(256, 3) fused_pre(
    const float* __restrict__ x,
    const float* __restrict__ g1, const float* __restrict__ b1,
    const float* __restrict__ sw, const float* __restrict__ sb,
    const float* __restrict__ g2, const float* __restrict__ b2)
{
    extern __shared__ float sm[];
    float* s_n = sm;               // [49][128]
    float* s_w = sm + WS2 * 128;   // [196][52]

    const int tid = threadIdx.x, lane = tid & 31, warp = tid >> 5;
    const int win = blockIdx.x;
    const int b = win / 81, wi = win % 81;
    const int wh = wi / 9, ww = wi % 9;
    const int c0 = lane * 4, headL = lane >> 3;
    const float* xb = x + (size_t)b * 3136 * 128;

    {   // x tile load (j advances by 2 rows per step)
        int jw = tid >> 7, jh = 0;
        int c = tid & 127;
        for (int idx = tid; idx < 6272; idx += 256) {
            int hs = wh * 7 + jh - 4, ws = ww * 7 + jw - 4;
            float v = 0.0f;
            if ((unsigned)hs < 56u && (unsigned)ws < 56u)
                v = xb[(hs * 56 + ws) * 128 + c];
            s_n[idx] = v;
            jw += 2; if (jw >= 7) { jw -= 7; jh++; }
        }
    }
    {   // weights
        int row = tid / 49, col = tid - 49 * row;
        for (int idx = tid; idx < 9604; idx += 256) {
            s_w[row * WPAD + col] = sw[idx];
            row += 5; col += 11;
            if (col >= 49) { col -= 49; row++; }
        }
    }
    __syncthreads();

    {   // LN1 in place (pad rows stay zero); direct i/7 indexing
        const float4 g1v = *(const float4*)(g1 + c0);
        const float4 b1v = *(const float4*)(b1 + c0);
        #pragma unroll
        for (int ii = 0; ii < 7; ii++) {
            int i = warp + 8 * ii;
            if (i >= 49) continue;
            int ih = i / 7, iw = i - 7 * ih;
            int hs = wh * 7 + ih - 4, ws = ww * 7 + iw - 4;
            if ((unsigned)hs >= 56u || (unsigned)ws >= 56u) continue;
            float4 v = *(float4*)(s_n + i * 128 + c0);
            float s = v.x + v.y + v.z + v.w;
            float s2 = v.x*v.x + v.y*v.y + v.z*v.z + v.w*v.w;
            #pragma unroll
            for (int o = 16; o; o >>= 1) {
                s  += __shfl_xor_sync(0xffffffffu, s,  o);
                s2 += __shfl_xor_sync(0xffffffffu, s2, o);
            }
            float mu = s * 0.0078125f;
            float inv = rsqrtf(s2 * 0.0078125f - mu * mu + 1e-5f);
            v.x = (v.x - mu) * inv * g1v.x + b1v.x;
            v.y = (v.y - mu) * inv * g1v.y + b1v.y;
            v.z = (v.z - mu) * inv * g1v.z + b1v.z;
            v.w = (v.w - mu) * inv * g1v.w + b1v.w;
            *(float4*)(s_n + i * 128 + c0) = v;
        }
    }
    __syncthreads();

    // two row-passes to bound register pressure
    #pragma unroll
    for (int g = 0; g < 2; g++) {
        const int NR = g ? 3 : 4;
        float4 acc[4];
        #pragma unroll
        for (int r = 0; r < 4; r++) {
            if (r >= NR) continue;
            int i = warp + 8 * (g * 4 + r);
            float bv = (i < 49) ? sb[headL * 49 + i] : 0.0f;
            acc[r] = make_float4(bv, bv, bv, bv);
        }
        const float* wbase = s_w + headL * 49 * WPAD;
        for (int j0 = 0; j0 < 48; j0 += 4) {
            float4 x0 = *(float4*)(s_n + (j0+0)*128 + c0);
            float4 x1 = *(float4*)(s_n + (j0+1)*128 + c0);
            float4 x2v = *(float4*)(s_n + (j0+2)*128 + c0);
            float4 x3 = *(float4*)(s_n + (j0+3)*128 + c0);
            #pragma unroll
            for (int r = 0; r < 4; r++) {
                if (r >= NR) continue;
                int i = warp + 8 * (g * 4 + r);
                if (i >= 49) continue;
                float4 wv = *(float4*)(wbase + i * WPAD + j0);
                acc[r].x += wv.x*x0.x + wv.y*x1.x + wv.z*x2v.x + wv.w*x3.x;
                acc[r].y += wv.x*x0.y + wv.y*x1.y + wv.z*x2v.y + wv.w*x3.y;
                acc[r].z += wv.x*x0.z + wv.y*x1.z + wv.z*x2v.z + wv.w*x3.z;
                acc[r].w += wv.x*x0.w + wv.y*x1.w + wv.z*x2v.w + wv.w*x3.w;
            }
        }
        {
            float4 xv = *(float4*)(s_n + 48*128 + c0);
            #pragma unroll
            for (int r = 0; r < 4; r++) {
                if (r >= NR) continue;
                int i = warp + 8 * (g * 4 + r);
                if (i >= 49) continue;
                float wv = wbase[i * WPAD + 48];
                acc[r].x += wv*xv.x; acc[r].y += wv*xv.y;
                acc[r].z += wv*xv.z; acc[r].w += wv*xv.w;
            }
        }
        const float4 g2v = *(const float4*)(g2 + c0);
        const float4 b2v = *(const float4*)(b2 + c0);
        #pragma unroll
        for (int r = 0; r < 4; r++) {
            if (r >= NR) continue;
            int i = warp + 8 * (g * 4 + r);
            if (i >= 49) continue;
            int ih = i / 7, iw = i - 7 * ih;
            int hs = wh * 7 + ih - 4, ws = ww * 7 + iw - 4;
            if ((unsigned)hs >= 56u || (unsigned)ws >= 56u) continue;
            size_t o = ((size_t)b * 3136 + hs * 56 + ws) * 128 + c0;
            float4 v = *(const float4*)(x + o);
            v.x += acc[r].x; v.y += acc[r].y; v.z += acc[r].z; v.w += acc[r].w;
            *(float4*)(g_x2 + o) = v;
            float s = v.x + v.y + v.z + v.w;
            float s2 = v.x*v.x + v.y*v.y + v.z*v.z + v.w*v.w;
            #pragma unroll
            for (int os = 16; os; os >>= 1) {
                s  += __shfl_xor_sync(0xffffffffu, s,  os);
                s2 += __shfl_xor_sync(0xffffffffu, s2, os);
            }
            float mu = s * 0.0078125f;
            float inv = rsqrtf(s2 * 0.0078125f - mu * mu + 1e-5f);
            float n0 = (v.x - mu) * inv * g2v.x + b2v.x;
            float n1 = (v.y - mu) * inv * g2v.y + b2v.y;
            float n2 = (v.z - mu) * inv * g2v.z + b2v.z;
            float n3 = (v.w - mu) * inv * g2v.w + b2v.w;
            *(uint2*)(g_xn + o) = make_uint2(pack_bf16(n0, n1), pack_bf16(n2, n3));
        }
    }
}

// =====================================================================
// Fused MLP: out = x2 + gelu(xn@W1 + b1)@W2 + b2, h stays in registers.
// =====================================================================
#define SXS   136
#define SW1S  136
#define SW2S  40
#define OFF_W1 34816
#define OFF_W2 (34816 + 2*8704)
#define OFF_B1 (OFF_W2 + 2*10240)
#define MLP_SMEM (OFF_B1 + 2048)   // 76800 B

__global__ void __launch_bounds__(256, 2)
mlp_fused(const float* __restrict__ bias1, const float* __restrict__ bias2,
          float* __restrict__ out)
{
    extern __shared__ char smem[];
    __nv_bfloat16* s_x  = (__nv_bfloat16*)smem;              // [128][136]
    const float*   s_b1 = (const float*)(smem + OFF_B1);     // [512]
    const uint32_t su = (uint32_t)__cvta_generic_to_shared(smem);

    const int tid = threadIdx.x, lane = tid & 31, warp = tid >> 5;
    const int t4 = lane >> 2, q = lane & 3;
    const int bm = blockIdx.x * 128;

    auto load_chunk = [&](int s) {
        uint32_t buf = (uint32_t)(s & 1);
        int n0 = s * 32;
        #pragma unroll
        for (int i = 0; i < 2; i++) {               // W1 chunk [32][128]
            int l = tid + 256 * i;
            int r = l >> 4, c = l & 15;
            cpasync16(su + OFF_W1 + buf * 8704 + r * 272 + c * 16,
                      g_w1t + (size_t)(n0 + r) * 128 + c * 8);
        }
        #pragma unroll
        for (int i = 0; i < 2; i++) {               // W2 chunk [128][32]
            int l = tid + 256 * i;
            int r = l >> 2, c = l & 3;
            cpasync16(su + OFF_W2 + buf * 10240 + r * 80 + c * 16,
                      g_w2t + (size_t)r * 512 + n0 + c * 8);
        }
        cp_commit();
    };

    #pragma unroll
    for (int i = 0; i < 8; i++) {
        int l = tid + 256 * i;
        int r = l >> 4, c = l & 15;
        cpasync16(su + r * 272 + c * 16, g_xn + (size_t)(bm + r) * 128 + c * 8);
    }
    if (tid < 128) cpasync16(su + OFF_B1 + tid * 16, bias1 + tid * 4);
    load_chunk(0);
    load_chunk(1);

    float oacc[16][4];
    #pragma unroll
    for (int i = 0; i < 16; i++)
        #pragma unroll
        for (int j = 0; j < 4; j++) oacc[i][j] = 0.0f;

    cp_wait<1>();
    __syncthreads();

    for (int s = 0; s < 16; s++) {
        const __nv_bfloat16* w1b = (const __nv_bfloat16*)(smem + OFF_W1 + (s & 1) * 8704);
        const __nv_bfloat16* w2b = (const __nv_bfloat16*)(smem + OFF_W2 + (s & 1) * 10240);

        float h[4][4];
        #pragma unroll
        for (int i = 0; i < 4; i++)
            #pragma unroll
            for (int j = 0; j < 4; j++) h[i][j] = 0.0f;
        #pragma unroll
        for (int kt = 0; kt < 8; kt++) {
            uint32_t a[4];
            const __nv_bfloat16* xr = s_x + (warp * 16 + t4) * SXS + kt * 16 + 2 * q;
            a[0] = *(const uint32_t*)xr;
            a[1] = *(const uint32_t*)(xr + 8 * SXS);
            a[2] = *(const uint32_t*)(xr + 8);
            a[3] = *(const uint32_t*)(xr + 8 * SXS + 8);
            #pragma unroll
            for (int ni = 0; ni < 4; ni++) {
                const __nv_bfloat16* wr = w1b + (ni * 8 + t4) * SW1S + kt * 16 + 2 * q;
                uint32_t b0 = *(const uint32_t*)wr;
                uint32_t b1 = *(const uint32_t*)(wr + 8);
                MMA16816(h[ni], a, b0, b1);
            }
        }
        uint32_t a2[2][4];
        #pragma unroll
        for (int ni = 0; ni < 4; ni++) {
            int col = s * 32 + ni * 8 + 2 * q;
            float ba = s_b1[col], bb = s_b1[col + 1];
            float v0 = gelu_exact(h[ni][0] + ba), v1 = gelu_exact(h[ni][1] + bb);
            float v2 = gelu_exact(h[ni][2] + ba), v3 = gelu_exact(h[ni][3] + bb);
            a2[ni >> 1][(ni & 1) * 2 + 0] = pack_bf16(v0, v1);
            a2[ni >> 1][(ni & 1) * 2 + 1] = pack_bf16(v2, v3);
        }
        #pragma unroll
        for (int kt2 = 0; kt2 < 2; kt2++)
            #pragma unroll
            for (int ni2 = 0; ni2 < 16; ni2++) {
                const __nv_bfloat16* wr = w2b + (ni2 * 8 + t4) * SW2S + kt2 * 16 + 2 * q;
                uint32_t b0 = *(const uint32_t*)wr;
                uint32_t b1 = *(const uint32_t*)(wr + 8);
                MMA16816(oacc[ni2], a2[kt2], b0, b1);
            }

        __syncthreads();
        if (s + 1 < 16) {
            if (s + 2 < 16) { load_chunk(s + 2); cp_wait<1>(); }
            else            { cp_wait<0>(); }
            __syncthreads();
        }
    }

    const int r0 = bm + warp * 16 + t4;
    #pragma unroll
    for (int ni2 = 0; ni2 < 16; ni2++) {
        int col = ni2 * 8 + 2 * q;
        float bs0 = __ldg(bias2 + col), bs1 = __ldg(bias2 + col + 1);
        float2 ra = *(const float2*)(g_x2 + (size_t)r0 * 128 + col);
        float2 rb = *(const float2*)(g_x2 + (size_t)(r0 + 8) * 128 + col);
        *(float2*)(out + (size_t)r0 * 128 + col) =
            make_float2(oacc[ni2][0] + bs0 + ra.x, oacc[ni2][1] + bs1 + ra.y);
        *(float2*)(out + (size_t)(r0 + 8) * 128 + col) =
            make_float2(oacc[ni2][2] + bs0 + rb.x, oacc[ni2][3] + bs1 + rb.y);
    }
}

// ---------- launch ----------
extern "C" void kernel_launch(void* const* d_in, const int* in_sizes, int n_in,
                              void* d_out, int out_size)
{
    const float* x   = (const float*)d_in[0];
    const float* g1  = (const float*)d_in[1];
    const float* b1  = (const float*)d_in[2];
    const float* sw  = (const float*)d_in[3];
    const float* sb  = (const float*)d_in[4];
    const float* g2  = (const float*)d_in[5];
    const float* b2  = (const float*)d_in[6];
    const float* w1  = (const float*)d_in[7];
    const float* bb1 = (const float*)d_in[8];
    const float* w2  = (const float*)d_in[9];
    const float* bb2 = (const float*)d_in[10];
    float* out = (float*)d_out;

    cudaFuncSetAttribute(fused_pre, cudaFuncAttributeMaxDynamicSharedMemorySize, PRE_SMEM);
    cudaFuncSetAttribute(mlp_fused, cudaFuncAttributeMaxDynamicSharedMemorySize, MLP_SMEM);

    prep_weights<<<256, 256>>>(w1, w2);
    fused_pre<<<NWIN, 256, PRE_SMEM>>>(x, g1, b1, sw, sb, g2, b2);
    mlp_fused<<<NTOK / 128, 256, MLP_SMEM>>>(bb1, bb2, out);
}

// round 8
// speedup vs baseline: 1.9536x; 1.1117x over previous
#include <cuda_runtime.h>
#include <cuda_bf16.h>
#include <math.h>
#include <stdint.h>

#define NTOK 200704
#define NWIN 5184

__device__ __nv_bfloat16 g_xn [(size_t)NTOK * 128];
__device__ float         g_x2 [(size_t)NTOK * 128];
__device__ __nv_bfloat16 g_w1t[512 * 128];        // [n][k]
__device__ __nv_bfloat16 g_w2t[128 * 512];        // [n][k]
__device__ __nv_bfloat16 g_swb[4 * 56 * 66];      // padded spatial w, [h][i(56)][j(66)]

__device__ __forceinline__ void cpasync16(uint32_t s, const void* g) {
    asm volatile("cp.async.cg.shared.global [%0], [%1], 16;\n" :: "r"(s), "l"(g));
}
__device__ __forceinline__ void cp_commit() { asm volatile("cp.async.commit_group;"); }
template<int N> __device__ __forceinline__ void cp_wait() {
    asm volatile("cp.async.wait_group %0;" :: "n"(N));
}
__device__ __forceinline__ uint32_t pack_bf16(float lo, float hi) {
    uint32_t r; asm("cvt.rn.bf16x2.f32 %0, %1, %2;" : "=r"(r) : "f"(hi), "f"(lo)); return r;
}
__device__ __forceinline__ float gelu_exact(float v) {
    return 0.5f * v * (1.0f + erff(v * 0.70710678118654752f));
}
#define MMA16816(d, a, b0, b1) \
    asm volatile("mma.sync.aligned.m16n8k16.row.col.f32.bf16.bf16.f32 " \
        "{%0,%1,%2,%3},{%4,%5,%6,%7},{%8,%9},{%0,%1,%2,%3};\n" \
        : "+f"((d)[0]), "+f"((d)[1]), "+f"((d)[2]), "+f"((d)[3]) \
        : "r"((a)[0]), "r"((a)[1]), "r"((a)[2]), "r"((a)[3]), "r"(b0), "r"(b1))

// ---------- weight prep ----------
__global__ void prep_weights(const float* __restrict__ w1, const float* __restrict__ w2,
                             const float* __restrict__ sw)
{
    int t = blockIdx.x * 256 + threadIdx.x;
    if (t < 512 * 128) {
        int n = t >> 7, k = t & 127;
        g_w1t[t] = __float2bfloat16(w1[k * 512 + n]);
        int n2 = t >> 9, k2 = t & 511;
        g_w2t[t] = __float2bfloat16(w2[k2 * 128 + n2]);
    }
    if (t < 4 * 56 * 66) {
        int h = t / 3696, r = t % 3696;
        int i = r / 66, j = r % 66;
        float v = (i < 49 && j < 49) ? sw[h * 2401 + i * 49 + j] : 0.0f;
        g_swb[t] = __float2bfloat16(v);
    }
}

// ---------- fused LN1 + tensor-core window mix + residual + LN2 ----------
#define SXT 66
#define SWS 66
#define SYS 57
#define OFF_SW 16896                    // 128*66*2
#define OFF_SY (16896 + 29568)          // + 4*56*66*2
#define PRE_SMEM (OFF_SY + 29184)       // + 128*57*4 = 75648

__global__ void __launch_bounds__(256, 3) fused_pre(
    const float* __restrict__ x,
    const float* __restrict__ g1, const float* __restrict__ b1,
    const float* __restrict__ sb,
    const float* __restrict__ g2, const float* __restrict__ b2)
{
    extern __shared__ char smem[];
    __nv_bfloat16* s_xt = (__nv_bfloat16*)smem;            // [128][66] = xn^T (bf16)
    __nv_bfloat16* s_w  = (__nv_bfloat16*)(smem + OFF_SW); // [4][56][66]
    float*         s_y  = (float*)(smem + OFF_SY);         // [128][57] = y^T
    const uint32_t su = (uint32_t)__cvta_generic_to_shared(smem);

    const int tid = threadIdx.x, lane = tid & 31, warp = tid >> 5;
    const int t4 = lane >> 2, q = lane & 3;
    const int c0 = lane * 4, headL = lane >> 3;

    // padded spatial weights -> smem (once per CTA)
    for (int l = tid; l < 1848; l += 256)
        cpasync16(su + OFF_SW + l * 16, (const char*)g_swb + l * 16);
    cp_commit();
    // zero s_xt once (j-pad columns must stay 0 forever)
    for (int l = tid; l < 4224; l += 256)
        ((uint32_t*)smem)[l] = 0;
    cp_wait<0>();
    __syncthreads();

    const float4 g1v = *(const float4*)(g1 + c0);
    const float4 b1v = *(const float4*)(b1 + c0);
    const float4 g2v = *(const float4*)(g2 + c0);
    const float4 b2v = *(const float4*)(b2 + c0);

    for (int wl = 0; wl < 4; wl++) {
        const int win = blockIdx.x * 4 + wl;
        const int b = win / 81, wi = win % 81;
        const int wh = wi / 9, ww = wi % 9;
        const float* xb = x + (size_t)b * 3136 * 128;

        // ---- stage 1: LN1, store transposed bf16 (invalid tokens -> zeros) ----
        #pragma unroll
        for (int ii = 0; ii < 7; ii++) {
            int i = warp + 8 * ii;
            if (i >= 49) continue;
            int ih = i / 7, iw = i - 7 * ih;
            int hs = wh * 7 + ih - 4, ws = ww * 7 + iw - 4;
            uint32_t pk01 = 0, pk23 = 0;
            if ((unsigned)hs < 56u && (unsigned)ws < 56u) {
                float4 v = *(const float4*)(xb + (hs * 56 + ws) * 128 + c0);
                float s = v.x + v.y + v.z + v.w;
                float s2 = v.x*v.x + v.y*v.y + v.z*v.z + v.w*v.w;
                #pragma unroll
                for (int o = 16; o; o >>= 1) {
                    s  += __shfl_xor_sync(0xffffffffu, s,  o);
                    s2 += __shfl_xor_sync(0xffffffffu, s2, o);
                }
                float mu = s * 0.0078125f;
                float inv = rsqrtf(s2 * 0.0078125f - mu * mu + 1e-5f);
                float n0 = (v.x - mu) * inv * g1v.x + b1v.x;
                float n1 = (v.y - mu) * inv * g1v.y + b1v.y;
                float n2 = (v.z - mu) * inv * g1v.z + b1v.z;
                float n3 = (v.w - mu) * inv * g1v.w + b1v.w;
                pk01 = pack_bf16(n0, n1);
                pk23 = pack_bf16(n2, n3);
            }
            *(uint16_t*)&s_xt[(c0+0)*SXT + i] = (uint16_t)(pk01 & 0xffff);
            *(uint16_t*)&s_xt[(c0+1)*SXT + i] = (uint16_t)(pk01 >> 16);
            *(uint16_t*)&s_xt[(c0+2)*SXT + i] = (uint16_t)(pk23 & 0xffff);
            *(uint16_t*)&s_xt[(c0+3)*SXT + i] = (uint16_t)(pk23 >> 16);
        }
        __syncthreads();

        // ---- stage 2: y^T = xn^T @ w^T per head (tensor cores) ----
        {
            const int h = warp >> 1, mh = warp & 1;
            const __nv_bfloat16* At = s_xt + (h * 32 + mh * 16) * SXT;
            const __nv_bfloat16* Bw = s_w + h * 56 * SWS;
            uint32_t afr[4][4];
            #pragma unroll
            for (int ks = 0; ks < 4; ks++) {
                const __nv_bfloat16* ar = At + t4 * SXT + ks * 16 + 2 * q;
                afr[ks][0] = *(const uint32_t*)ar;
                afr[ks][1] = *(const uint32_t*)(ar + 8 * SXT);
                afr[ks][2] = *(const uint32_t*)(ar + 8);
                afr[ks][3] = *(const uint32_t*)(ar + 8 * SXT + 8);
            }
            #pragma unroll
            for (int nt = 0; nt < 7; nt++) {
                float c[4] = {0.f, 0.f, 0.f, 0.f};
                #pragma unroll
                for (int ks = 0; ks < 4; ks++) {
                    const __nv_bfloat16* br = Bw + (nt * 8 + t4) * SWS + ks * 16 + 2 * q;
                    uint32_t b0 = *(const uint32_t*)br;
                    uint32_t b1 = *(const uint32_t*)(br + 8);
                    MMA16816(c, afr[ks], b0, b1);
                }
                int crow = h * 32 + mh * 16 + t4;
                int i0 = nt * 8 + 2 * q;
                s_y[ crow      * SYS + i0    ] = c[0];
                s_y[ crow      * SYS + i0 + 1] = c[1];
                s_y[(crow + 8) * SYS + i0    ] = c[2];
                s_y[(crow + 8) * SYS + i0 + 1] = c[3];
            }
        }
        __syncthreads();

        // ---- stage 3: residual (re-read x) + spatial bias + LN2 + writes ----
        #pragma unroll
        for (int ii = 0; ii < 7; ii++) {
            int i = warp + 8 * ii;
            if (i >= 49) continue;
            int ih = i / 7, iw = i - 7 * ih;
            int hs = wh * 7 + ih - 4, ws = ww * 7 + iw - 4;
            if ((unsigned)hs >= 56u || (unsigned)ws >= 56u) continue;
            float sbv = sb[headL * 49 + i];
            float y0 = s_y[(c0+0)*SYS + i];
            float y1 = s_y[(c0+1)*SYS + i];
            float y2 = s_y[(c0+2)*SYS + i];
            float y3 = s_y[(c0+3)*SYS + i];
            size_t o = ((size_t)b * 3136 + hs * 56 + ws) * 128 + c0;
            float4 v = *(const float4*)(x + o);
            v.x += y0 + sbv; v.y += y1 + sbv; v.z += y2 + sbv; v.w += y3 + sbv;
            *(float4*)(g_x2 + o) = v;
            float s = v.x + v.y + v.z + v.w;
            float s2 = v.x*v.x + v.y*v.y + v.z*v.z + v.w*v.w;
            #pragma unroll
            for (int os = 16; os; os >>= 1) {
                s  += __shfl_xor_sync(0xffffffffu, s,  os);
                s2 += __shfl_xor_sync(0xffffffffu, s2, os);
            }
            float mu = s * 0.0078125f;
            float inv = rsqrtf(s2 * 0.0078125f - mu * mu + 1e-5f);
            float n0 = (v.x - mu) * inv * g2v.x + b2v.x;
            float n1 = (v.y - mu) * inv * g2v.y + b2v.y;
            float n2 = (v.z - mu) * inv * g2v.z + b2v.z;
            float n3 = (v.w - mu) * inv * g2v.w + b2v.w;
            *(uint2*)(g_xn + o) = make_uint2(pack_bf16(n0, n1), pack_bf16(n2, n3));
        }
        __syncthreads();
    }
}

// =====================================================================
// Fused MLP (unchanged from R7): out = x2 + gelu(xn@W1+b1)@W2 + b2
// =====================================================================
#define SXS   136
#define SW1S  136
#define SW2S  40
#define OFF_W1 34816
#define OFF_W2 (34816 + 2*8704)
#define OFF_B1 (OFF_W2 + 2*10240)
#define MLP_SMEM (OFF_B1 + 2048)

__global__ void __launch_bounds__(256, 2)
mlp_fused(const float* __restrict__ bias1, const float* __restrict__ bias2,
          float* __restrict__ out)
{
    extern __shared__ char smem[];
    __nv_bfloat16* s_x  = (__nv_bfloat16*)smem;
    const float*   s_b1 = (const float*)(smem + OFF_B1);
    const uint32_t su = (uint32_t)__cvta_generic_to_shared(smem);

    const int tid = threadIdx.x, lane = tid & 31, warp = tid >> 5;
    const int t4 = lane >> 2, q = lane & 3;
    const int bm = blockIdx.x * 128;

    auto load_chunk = [&](int s) {
        uint32_t buf = (uint32_t)(s & 1);
        int n0 = s * 32;
        #pragma unroll
        for (int i = 0; i < 2; i++) {
            int l = tid + 256 * i;
            int r = l >> 4, c = l & 15;
            cpasync16(su + OFF_W1 + buf * 8704 + r * 272 + c * 16,
                      g_w1t + (size_t)(n0 + r) * 128 + c * 8);
        }
        #pragma unroll
        for (int i = 0; i < 2; i++) {
            int l = tid + 256 * i;
            int r = l >> 2, c = l & 3;
            cpasync16(su + OFF_W2 + buf * 10240 + r * 80 + c * 16,
                      g_w2t + (size_t)r * 512 + n0 + c * 8);
        }
        cp_commit();
    };

    #pragma unroll
    for (int i = 0; i < 8; i++) {
        int l = tid + 256 * i;
        int r = l >> 4, c = l & 15;
        cpasync16(su + r * 272 + c * 16, g_xn + (size_t)(bm + r) * 128 + c * 8);
    }
    if (tid < 128) cpasync16(su + OFF_B1 + tid * 16, bias1 + tid * 4);
    load_chunk(0);
    load_chunk(1);

    float oacc[16][4];
    #pragma unroll
    for (int i = 0; i < 16; i++)
        #pragma unroll
        for (int j = 0; j < 4; j++) oacc[i][j] = 0.0f;

    cp_wait<1>();
    __syncthreads();

    for (int s = 0; s < 16; s++) {
        const __nv_bfloat16* w1b = (const __nv_bfloat16*)(smem + OFF_W1 + (s & 1) * 8704);
        const __nv_bfloat16* w2b = (const __nv_bfloat16*)(smem + OFF_W2 + (s & 1) * 10240);

        float h[4][4];
        #pragma unroll
        for (int i = 0; i < 4; i++)
            #pragma unroll
            for (int j = 0; j < 4; j++) h[i][j] = 0.0f;
        #pragma unroll
        for (int kt = 0; kt < 8; kt++) {
            uint32_t a[4];
            const __nv_bfloat16* xr = s_x + (warp * 16 + t4) * SXS + kt * 16 + 2 * q;
            a[0] = *(const uint32_t*)xr;
            a[1] = *(const uint32_t*)(xr + 8 * SXS);
            a[2] = *(const uint32_t*)(xr + 8);
            a[3] = *(const uint32_t*)(xr + 8 * SXS + 8);
            #pragma unroll
            for (int ni = 0; ni < 4; ni++) {
                const __nv_bfloat16* wr = w1b + (ni * 8 + t4) * SW1S + kt * 16 + 2 * q;
                uint32_t b0 = *(const uint32_t*)wr;
                uint32_t b1 = *(const uint32_t*)(wr + 8);
                MMA16816(h[ni], a, b0, b1);
            }
        }
        uint32_t a2[2][4];
        #pragma unroll
        for (int ni = 0; ni < 4; ni++) {
            int col = s * 32 + ni * 8 + 2 * q;
            float ba = s_b1[col], bb = s_b1[col + 1];
            float v0 = gelu_exact(h[ni][0] + ba), v1 = gelu_exact(h[ni][1] + bb);
            float v2 = gelu_exact(h[ni][2] + ba), v3 = gelu_exact(h[ni][3] + bb);
            a2[ni >> 1][(ni & 1) * 2 + 0] = pack_bf16(v0, v1);
            a2[ni >> 1][(ni & 1) * 2 + 1] = pack_bf16(v2, v3);
        }
        #pragma unroll
        for (int kt2 = 0; kt2 < 2; kt2++)
            #pragma unroll
            for (int ni2 = 0; ni2 < 16; ni2++) {
                const __nv_bfloat16* wr = w2b + (ni2 * 8 + t4) * SW2S + kt2 * 16 + 2 * q;
                uint32_t b0 = *(const uint32_t*)wr;
                uint32_t b1 = *(const uint32_t*)(wr + 8);
                MMA16816(oacc[ni2], a2[kt2], b0, b1);
            }

        __syncthreads();
        if (s + 1 < 16) {
            if (s + 2 < 16) { load_chunk(s + 2); cp_wait<1>(); }
            else            { cp_wait<0>(); }
            __syncthreads();
        }
    }

    const int r0 = bm + warp * 16 + t4;
    #pragma unroll
    for (int ni2 = 0; ni2 < 16; ni2++) {
        int col = ni2 * 8 + 2 * q;
        float bs0 = __ldg(bias2 + col), bs1 = __ldg(bias2 + col + 1);
        float2 ra = *(const float2*)(g_x2 + (size_t)r0 * 128 + col);
        float2 rb = *(const float2*)(g_x2 + (size_t)(r0 + 8) * 128 + col);
        *(float2*)(out + (size_t)r0 * 128 + col) =
            make_float2(oacc[ni2][0] + bs0 + ra.x, oacc[ni2][1] + bs1 + ra.y);
        *(float2*)(out + (size_t)(r0 + 8) * 128 + col) =
            make_float2(oacc[ni2][2] + bs0 + rb.x, oacc[ni2][3] + bs1 + rb.y);
    }
}

// ---------- launch ----------
extern "C" void kernel_launch(void* const* d_in, const int* in_sizes, int n_in,
                              void* d_out, int out_size)
{
    const float* x   = (const float*)d_in[0];
    const float* g1  = (const float*)d_in[1];
    const float* b1  = (const float*)d_in[2];
    const float* sw  = (const float*)d_in[3];
    const float* sb  = (const float*)d_in[4];
    const float* g2  = (const float*)d_in[5];
    const float* b2  = (const float*)d_in[6];
    const float* w1  = (const float*)d_in[7];
    const float* bb1 = (const float*)d_in[8];
    const float* w2  = (const float*)d_in[9];
    const float* bb2 = (const float*)d_in[10];
    float* out = (float*)d_out;

    cudaFuncSetAttribute(fused_pre, cudaFuncAttributeMaxDynamicSharedMemorySize, PRE_SMEM);
    cudaFuncSetAttribute(mlp_fused, cudaFuncAttributeMaxDynamicSharedMemorySize, MLP_SMEM);

    prep_weights<<<256, 256>>>(w1, w2, sw);
    fused_pre<<<NWIN / 4, 256, PRE_SMEM>>>(x, g1, b1, sb, g2, b2);
    mlp_fused<<<NTOK / 128, 256, MLP_SMEM>>>(bb1, bb2, out);
}

// round 9
// speedup vs baseline: 2.0570x; 1.0529x over previous
#include <cuda_runtime.h>
#include <cuda_bf16.h>
#include <math.h>
#include <stdint.h>

#define NTOK 200704
#define NWIN 5184

__device__ __nv_bfloat16 g_xn [(size_t)NTOK * 128];
__device__ float         g_x2 [(size_t)NTOK * 128];
__device__ __nv_bfloat16 g_w1t[512 * 128];        // [n][k]
__device__ __nv_bfloat16 g_w2t[128 * 512];        // [n][k]
__device__ __nv_bfloat16 g_swb[4 * 56 * 72];      // padded spatial w [h][i(56)][j(72)]

__device__ __forceinline__ void cpasync16(uint32_t s, const void* g) {
    asm volatile("cp.async.cg.shared.global [%0], [%1], 16;\n" :: "r"(s), "l"(g));
}
__device__ __forceinline__ void cp_commit() { asm volatile("cp.async.commit_group;"); }
template<int N> __device__ __forceinline__ void cp_wait() {
    asm volatile("cp.async.wait_group %0;" :: "n"(N));
}
__device__ __forceinline__ uint32_t pack_bf16(float lo, float hi) {
    uint32_t r; asm("cvt.rn.bf16x2.f32 %0, %1, %2;" : "=r"(r) : "f"(hi), "f"(lo)); return r;
}
__device__ __forceinline__ float gelu_exact(float v) {
    return 0.5f * v * (1.0f + erff(v * 0.70710678118654752f));
}
__device__ __forceinline__ void ldmx4t(uint32_t* r, uint32_t saddr) {
    asm volatile("ldmatrix.sync.aligned.m8n8.x4.trans.shared.b16 {%0,%1,%2,%3}, [%4];"
        : "=r"(r[0]), "=r"(r[1]), "=r"(r[2]), "=r"(r[3]) : "r"(saddr));
}
#define MMA16816(d, a, b0, b1) \
    asm volatile("mma.sync.aligned.m16n8k16.row.col.f32.bf16.bf16.f32 " \
        "{%0,%1,%2,%3},{%4,%5,%6,%7},{%8,%9},{%0,%1,%2,%3};\n" \
        : "+f"((d)[0]), "+f"((d)[1]), "+f"((d)[2]), "+f"((d)[3]) \
        : "r"((a)[0]), "r"((a)[1]), "r"((a)[2]), "r"((a)[3]), "r"(b0), "r"(b1))

// ---------- weight prep ----------
__global__ void prep_weights(const float* __restrict__ w1, const float* __restrict__ w2,
                             const float* __restrict__ sw)
{
    int t = blockIdx.x * 256 + threadIdx.x;
    if (t < 512 * 128) {
        int n = t >> 7, k = t & 127;
        g_w1t[t] = __float2bfloat16(w1[k * 512 + n]);
        int n2 = t >> 9, k2 = t & 511;
        g_w2t[t] = __float2bfloat16(w2[k2 * 128 + n2]);
    }
    if (t < 4 * 56 * 72) {
        int h = t / 4032, r = t % 4032;
        int i = r / 72, j = r % 72;
        float v = (i < 49 && j < 49) ? sw[h * 2401 + i * 49 + j] : 0.0f;
        g_swb[t] = __float2bfloat16(v);
    }
}

// ---------- fused LN1 + tensor-core window mix + residual + LN2 ----------
#define SXP 136          // s_xn stride (bf16): 272B rows -> ldmatrix conflict-free
#define SWS 72           // s_w stride (bf16): B-frag LDS conflict-free
#define SYP 132          // s_y stride (f32): conflict-free frag writes + float4 reads
#define OFF_W  17408     // 64*136*2
#define OFF_Y  (OFF_W + 32256)          // + 4*56*72*2
#define PRE_SMEM (OFF_Y + 29568)        // + 56*132*4 = 79232

__global__ void __launch_bounds__(256, 2) fused_pre(
    const float* __restrict__ x,
    const float* __restrict__ g1, const float* __restrict__ b1,
    const float* __restrict__ sb,
    const float* __restrict__ g2, const float* __restrict__ b2)
{
    extern __shared__ char smem[];
    __nv_bfloat16* s_xn = (__nv_bfloat16*)smem;            // [64][136] LN1 row-major
    __nv_bfloat16* s_w  = (__nv_bfloat16*)(smem + OFF_W);  // [4][56][72]
    float*         s_y  = (float*)(smem + OFF_Y);          // [56][132] y[i][c]
    const uint32_t su = (uint32_t)__cvta_generic_to_shared(smem);

    const int tid = threadIdx.x, lane = tid & 31, warp = tid >> 5;
    const int t4 = lane >> 2, q = lane & 3;
    const int c0 = lane * 4, headL = lane >> 3;

    // spatial weights -> smem (once)
    for (int l = tid; l < 2016; l += 256)
        cpasync16(su + OFF_W + l * 16, (const char*)g_swb + l * 16);
    cp_commit();
    // zero s_xn once (rows 49..63 must stay zero; rows 0..48 rewritten per window)
    for (int l = tid; l < 4352; l += 256)
        ((uint32_t*)smem)[l] = 0;
    cp_wait<0>();
    __syncthreads();

    const float4 g1v = *(const float4*)(g1 + c0);
    const float4 b1v = *(const float4*)(b1 + c0);
    const float4 g2v = *(const float4*)(g2 + c0);
    const float4 b2v = *(const float4*)(b2 + c0);

    const int h = warp >> 1, mh = warp & 1;
    const int cbase = h * 32 + mh * 16;

    for (int wl = 0; wl < 4; wl++) {
        const int win = blockIdx.x * 4 + wl;
        const int b = win / 81, wi = win % 81;
        const int wh = wi / 9, ww = wi % 9;
        const float* xb = x + (size_t)b * 3136 * 128;

        // ---- stage 1: LN1 -> row-major bf16; keep raw x in registers ----
        float4 xv[7];
        #pragma unroll
        for (int ii = 0; ii < 7; ii++) {
            int i = warp + 8 * ii;
            if (i >= 49) continue;
            int ih = i / 7, iw = i - 7 * ih;
            int hs = wh * 7 + ih - 4, ws = ww * 7 + iw - 4;
            uint2 pk = make_uint2(0u, 0u);
            if ((unsigned)hs < 56u && (unsigned)ws < 56u) {
                float4 v = *(const float4*)(xb + (hs * 56 + ws) * 128 + c0);
                xv[ii] = v;
                float s = v.x + v.y + v.z + v.w;
                float s2 = v.x*v.x + v.y*v.y + v.z*v.z + v.w*v.w;
                #pragma unroll
                for (int o = 16; o; o >>= 1) {
                    s  += __shfl_xor_sync(0xffffffffu, s,  o);
                    s2 += __shfl_xor_sync(0xffffffffu, s2, o);
                }
                float mu = s * 0.0078125f;
                float inv = rsqrtf(s2 * 0.0078125f - mu * mu + 1e-5f);
                pk.x = pack_bf16((v.x - mu) * inv * g1v.x + b1v.x,
                                 (v.y - mu) * inv * g1v.y + b1v.y);
                pk.y = pack_bf16((v.z - mu) * inv * g1v.z + b1v.z,
                                 (v.w - mu) * inv * g1v.w + b1v.w);
            }
            *(uint2*)&s_xn[i * SXP + c0] = pk;
        }
        __syncthreads();

        // ---- stage 2: y^T = xn^T @ w^T per head (ldmatrix.trans + mma) ----
        {
            uint32_t afr[4][4];
            const int g = lane >> 3, lr = lane & 7;
            #pragma unroll
            for (int ks = 0; ks < 4; ks++) {
                int j = ks * 16 + (g >> 1) * 8 + lr;
                int cb = cbase + (g & 1) * 8;
                ldmx4t(afr[ks], su + (uint32_t)((j * SXP + cb) * 2));
            }
            const __nv_bfloat16* Bw = s_w + h * 56 * SWS;
            #pragma unroll
            for (int nt = 0; nt < 7; nt++) {
                float c[4] = {0.f, 0.f, 0.f, 0.f};
                #pragma unroll
                for (int ks = 0; ks < 4; ks++) {
                    const __nv_bfloat16* br = Bw + (nt * 8 + t4) * SWS + ks * 16 + 2 * q;
                    uint32_t b0 = *(const uint32_t*)br;
                    uint32_t b1 = *(const uint32_t*)(br + 8);
                    MMA16816(c, afr[ks], b0, b1);
                }
                int i0 = nt * 8 + 2 * q;
                int crow = cbase + t4;
                s_y[ i0      * SYP + crow    ] = c[0];
                s_y[(i0 + 1) * SYP + crow    ] = c[1];
                s_y[ i0      * SYP + crow + 8] = c[2];
                s_y[(i0 + 1) * SYP + crow + 8] = c[3];
            }
        }
        __syncthreads();

        // ---- stage 3: residual (x from regs) + bias + LN2 + global writes ----
        #pragma unroll
        for (int ii = 0; ii < 7; ii++) {
            int i = warp + 8 * ii;
            if (i >= 49) continue;
            int ih = i / 7, iw = i - 7 * ih;
            int hs = wh * 7 + ih - 4, ws = ww * 7 + iw - 4;
            if ((unsigned)hs >= 56u || (unsigned)ws >= 56u) continue;
            float sbv = sb[headL * 49 + i];
            float4 y4 = *(const float4*)(s_y + i * SYP + c0);
            float4 v = xv[ii];
            v.x += y4.x + sbv; v.y += y4.y + sbv;
            v.z += y4.z + sbv; v.w += y4.w + sbv;
            size_t o = ((size_t)b * 3136 + hs * 56 + ws) * 128 + c0;
            *(float4*)(g_x2 + o) = v;
            float s = v.x + v.y + v.z + v.w;
            float s2 = v.x*v.x + v.y*v.y + v.z*v.z + v.w*v.w;
            #pragma unroll
            for (int os = 16; os; os >>= 1) {
                s  += __shfl_xor_sync(0xffffffffu, s,  os);
                s2 += __shfl_xor_sync(0xffffffffu, s2, os);
            }
            float mu = s * 0.0078125f;
            float inv = rsqrtf(s2 * 0.0078125f - mu * mu + 1e-5f);
            float n0 = (v.x - mu) * inv * g2v.x + b2v.x;
            float n1 = (v.y - mu) * inv * g2v.y + b2v.y;
            float n2 = (v.z - mu) * inv * g2v.z + b2v.z;
            float n3 = (v.w - mu) * inv * g2v.w + b2v.w;
            *(uint2*)(g_xn + o) = make_uint2(pack_bf16(n0, n1), pack_bf16(n2, n3));
        }
        // no barrier needed here: next stage-1 sync orders s_y reuse
    }
}

// =====================================================================
// Fused MLP (unchanged, passing): out = x2 + gelu(xn@W1+b1)@W2 + b2
// =====================================================================
#define SXS   136
#define SW1S  136
#define SW2S  40
#define OFF_W1 34816
#define OFF_W2 (34816 + 2*8704)
#define OFF_B1 (OFF_W2 + 2*10240)
#define MLP_SMEM (OFF_B1 + 2048)

__global__ void __launch_bounds__(256, 2)
mlp_fused(const float* __restrict__ bias1, const float* __restrict__ bias2,
          float* __restrict__ out)
{
    extern __shared__ char smem[];
    __nv_bfloat16* s_x  = (__nv_bfloat16*)smem;
    const float*   s_b1 = (const float*)(smem + OFF_B1);
    const uint32_t su = (uint32_t)__cvta_generic_to_shared(smem);

    const int tid = threadIdx.x, lane = tid & 31, warp = tid >> 5;
    const int t4 = lane >> 2, q = lane & 3;
    const int bm = blockIdx.x * 128;

    auto load_chunk = [&](int s) {
        uint32_t buf = (uint32_t)(s & 1);
        int n0 = s * 32;
        #pragma unroll
        for (int i = 0; i < 2; i++) {
            int l = tid + 256 * i;
            int r = l >> 4, c = l & 15;
            cpasync16(su + OFF_W1 + buf * 8704 + r * 272 + c * 16,
                      g_w1t + (size_t)(n0 + r) * 128 + c * 8);
        }
        #pragma unroll
        for (int i = 0; i < 2; i++) {
            int l = tid + 256 * i;
            int r = l >> 2, c = l & 3;
            cpasync16(su + OFF_W2 + buf * 10240 + r * 80 + c * 16,
                      g_w2t + (size_t)r * 512 + n0 + c * 8);
        }
        cp_commit();
    };

    #pragma unroll
    for (int i = 0; i < 8; i++) {
        int l = tid + 256 * i;
        int r = l >> 4, c = l & 15;
        cpasync16(su + r * 272 + c * 16, g_xn + (size_t)(bm + r) * 128 + c * 8);
    }
    if (tid < 128) cpasync16(su + OFF_B1 + tid * 16, bias1 + tid * 4);
    load_chunk(0);
    load_chunk(1);

    float oacc[16][4];
    #pragma unroll
    for (int i = 0; i < 16; i++)
        #pragma unroll
        for (int j = 0; j < 4; j++) oacc[i][j] = 0.0f;

    cp_wait<1>();
    __syncthreads();

    for (int s = 0; s < 16; s++) {
        const __nv_bfloat16* w1b = (const __nv_bfloat16*)(smem + OFF_W1 + (s & 1) * 8704);
        const __nv_bfloat16* w2b = (const __nv_bfloat16*)(smem + OFF_W2 + (s & 1) * 10240);

        float h[4][4];
        #pragma unroll
        for (int i = 0; i < 4; i++)
            #pragma unroll
            for (int j = 0; j < 4; j++) h[i][j] = 0.0f;
        #pragma unroll
        for (int kt = 0; kt < 8; kt++) {
            uint32_t a[4];
            const __nv_bfloat16* xr = s_x + (warp * 16 + t4) * SXS + kt * 16 + 2 * q;
            a[0] = *(const uint32_t*)xr;
            a[1] = *(const uint32_t*)(xr + 8 * SXS);
            a[2] = *(const uint32_t*)(xr + 8);
            a[3] = *(const uint32_t*)(xr + 8 * SXS + 8);
            #pragma unroll
            for (int ni = 0; ni < 4; ni++) {
                const __nv_bfloat16* wr = w1b + (ni * 8 + t4) * SW1S + kt * 16 + 2 * q;
                uint32_t b0 = *(const uint32_t*)wr;
                uint32_t b1 = *(const uint32_t*)(wr + 8);
                MMA16816(h[ni], a, b0, b1);
            }
        }
        uint32_t a2[2][4];
        #pragma unroll
        for (int ni = 0; ni < 4; ni++) {
            int col = s * 32 + ni * 8 + 2 * q;
            float ba = s_b1[col], bb = s_b1[col + 1];
            float v0 = gelu_exact(h[ni][0] + ba), v1 = gelu_exact(h[ni][1] + bb);
            float v2 = gelu_exact(h[ni][2] + ba), v3 = gelu_exact(h[ni][3] + bb);
            a2[ni >> 1][(ni & 1) * 2 + 0] = pack_bf16(v0, v1);
            a2[ni >> 1][(ni & 1) * 2 + 1] = pack_bf16(v2, v3);
        }
        #pragma unroll
        for (int kt2 = 0; kt2 < 2; kt2++)
            #pragma unroll
            for (int ni2 = 0; ni2 < 16; ni2++) {
                const __nv_bfloat16* wr = w2b + (ni2 * 8 + t4) * SW2S + kt2 * 16 + 2 * q;
                uint32_t b0 = *(const uint32_t*)wr;
                uint32_t b1 = *(const uint32_t*)(wr + 8);
                MMA16816(oacc[ni2], a2[kt2], b0, b1);
            }

        __syncthreads();
        if (s + 1 < 16) {
            if (s + 2 < 16) { load_chunk(s + 2); cp_wait<1>(); }
            else            { cp_wait<0>(); }
            __syncthreads();
        }
    }

    const int r0 = bm + warp * 16 + t4;
    #pragma unroll
    for (int ni2 = 0; ni2 < 16; ni2++) {
        int col = ni2 * 8 + 2 * q;
        float bs0 = __ldg(bias2 + col), bs1 = __ldg(bias2 + col + 1);
        float2 ra = *(const float2*)(g_x2 + (size_t)r0 * 128 + col);
        float2 rb = *(const float2*)(g_x2 + (size_t)(r0 + 8) * 128 + col);
        *(float2*)(out + (size_t)r0 * 128 + col) =
            make_float2(oacc[ni2][0] + bs0 + ra.x, oacc[ni2][1] + bs1 + ra.y);
        *(float2*)(out + (size_t)(r0 + 8) * 128 + col) =
            make_float2(oacc[ni2][2] + bs0 + rb.x, oacc[ni2][3] + bs1 + rb.y);
    }
}

// ---------- launch ----------
extern "C" void kernel_launch(void* const* d_in, const int* in_sizes, int n_in,
                              void* d_out, int out_size)
{
    const float* x   = (const float*)d_in[0];
    const float* g1  = (const float*)d_in[1];
    const float* b1  = (const float*)d_in[2];
    const float* sw  = (const float*)d_in[3];
    const float* sb  = (const float*)d_in[4];
    const float* g2  = (const float*)d_in[5];
    const float* b2  = (const float*)d_in[6];
    const float* w1  = (const float*)d_in[7];
    const float* bb1 = (const float*)d_in[8];
    const float* w2  = (const float*)d_in[9];
    const float* bb2 = (const float*)d_in[10];
    float* out = (float*)d_out;

    cudaFuncSetAttribute(fused_pre, cudaFuncAttributeMaxDynamicSharedMemorySize, PRE_SMEM);
    cudaFuncSetAttribute(mlp_fused, cudaFuncAttributeMaxDynamicSharedMemorySize, MLP_SMEM);

    prep_weights<<<256, 256>>>(w1, w2, sw);
    fused_pre<<<NWIN / 4, 256, PRE_SMEM>>>(x, g1, b1, sb, g2, b2);
    mlp_fused<<<NTOK / 128, 256, MLP_SMEM>>>(bb1, bb2, out);
}